// round 13
// baseline (speedup 1.0000x reference)
#include <cuda_runtime.h>
#include <cstdint>

#define BB 128
#define TT 4096
#define KK 64
#define CHUNK 64
#define NCH   (TT / CHUNK)   /* 64 chunks */
#define GRP   8              /* chunks per backward group (32 KB) */
#define NBAT  2              /* batches per forward CTA */

// scratch (static __device__: allocation-free)
__device__ __align__(16) uint8_t g_bp[(size_t)BB * TT * KK];   // 32 MB backpointers
__device__ int g_lasttag[BB];

// dynamic smem: per-batch slabs
struct SmemB {
    float   ebuf[2][CHUNK * KK];         // 32 KB emission double buffer
    float   aslab[2][(CHUNK + 1) * KK];  // 32.5 KB alpha rows (row 0 = carry-in)
    float   bslab[2][CHUNK * KK];        // 32 KB per-step pre-emission max
    uint8_t bps[2][CHUNK * KK];          // 8 KB bp staging
};
struct Smem { SmemB bat[NBAT]; };        // ~211 KB

__device__ __forceinline__ void cpasync16(uint32_t saddr, const void* gptr) {
    asm volatile("cp.async.ca.shared.global [%0], [%1], 16;" :: "r"(saddr), "l"(gptr));
}
__device__ __forceinline__ void cpasync_commit() { asm volatile("cp.async.commit_group;"); }
__device__ __forceinline__ void cpasync_wait1()  { asm volatile("cp.async.wait_group 1;"); }

__device__ __forceinline__ unsigned long long addx2(unsigned long long a, unsigned long long b) {
    unsigned long long d;
    asm("add.rn.f32x2 %0, %1, %2;" : "=l"(d) : "l"(a), "l"(b));
    return d;
}
__device__ __forceinline__ unsigned long long fma2(unsigned long long a, unsigned long long b,
                                                   unsigned long long c) {
    unsigned long long d;
    asm("fma.rn.f32x2 %0, %1, %2, %3;" : "=l"(d) : "l"(a), "l"(b), "l"(c));
    return d;
}
__device__ __forceinline__ float lo32(unsigned long long x) { return __uint_as_float((unsigned)x); }
__device__ __forceinline__ float hi32(unsigned long long x) { return __uint_as_float((unsigned)(x >> 32)); }
__device__ __forceinline__ unsigned long long pk2(float a, float b) {
    return (unsigned long long)__float_as_uint(a) | ((unsigned long long)__float_as_uint(b) << 32);
}

#define NEG1X2 0xBF800000BF800000ULL   /* (-1, -1) */
#define BIGX2  0x5F0000005F000000ULL   /* (2^63, 2^63) */

// =====================================================================
// Warp-specialized forward, 2 batches per CTA (chain interleaving).
// Warps 0-3 (tid<128) = VALUE: run BOTH batches' serial max recursions
// interleaved — independent chains fill each other's latency stalls.
// Warps 4-11 = BP: each 128-thread half computes one batch's chunk-lagged
// argmax via float keys (d = RN(best-v) == +0 iff winner; key =
// RN(d*2^63 + j) == j exactly for winners; min-key = first-index argmax).
// =====================================================================
__global__ void __launch_bounds__(384, 1) fwd_kernel(const float* __restrict__ pot,
                                                     const float* __restrict__ trans) {
    extern __shared__ char smraw[];
    Smem* sm = (Smem*)smraw;

    const int b0   = blockIdx.x * NBAT;
    const int tid  = threadIdx.x;
    const bool isVal = (tid < 128);
    const int stid   = isVal ? tid : ((tid - 128) & 127);
    const int bslice = isVal ? 0 : ((tid - 128) >> 7);   // bp: batch index
    const int k  = stid >> 1;   // 0..63
    const int jh = stid & 1;    // 0..1

    unsigned long long trp[16];
#pragma unroll
    for (int i = 0; i < 16; ++i)
        trp[i] = pk2(trans[(jh * 32 + 2 * i) * KK + k],
                     trans[(jh * 32 + 2 * i + 1) * KK + k]);

    unsigned long long idxp[16];
    if (!isVal) {
#pragma unroll
        for (int i = 0; i < 16; ++i)
            idxp[i] = pk2((float)(jh * 32 + 2 * i), (float)(jh * 32 + 2 * i + 1));
    }

    const float* pb0 = pot + (size_t)b0 * TT * KK;
    const float* pb1 = pot + (size_t)(b0 + 1) * TT * KK;

    if (isVal) {   // prologue: prefetch chunks 0,1 for both batches
        uint32_t e00 = (uint32_t)__cvta_generic_to_shared(sm->bat[0].ebuf[0]);
        uint32_t e01 = (uint32_t)__cvta_generic_to_shared(sm->bat[0].ebuf[1]);
        uint32_t e10 = (uint32_t)__cvta_generic_to_shared(sm->bat[1].ebuf[0]);
        uint32_t e11 = (uint32_t)__cvta_generic_to_shared(sm->bat[1].ebuf[1]);
#pragma unroll
        for (int i = 0; i < 8; ++i) {
            cpasync16(e00 + (i * 128 + stid) * 16, pb0 + (i * 128 + stid) * 4);
            cpasync16(e10 + (i * 128 + stid) * 16, pb1 + (i * 128 + stid) * 4);
        }
        cpasync_commit();
#pragma unroll
        for (int i = 0; i < 8; ++i) {
            cpasync16(e01 + (i * 128 + stid) * 16, pb0 + CHUNK * KK + (i * 128 + stid) * 4);
            cpasync16(e11 + (i * 128 + stid) * 16, pb1 + CHUNK * KK + (i * 128 + stid) * 4);
        }
        cpasync_commit();
        cpasync_wait1();
    }
    __syncthreads();
    if (isVal && jh == 0) {
        sm->bat[0].aslab[0][KK + k] = sm->bat[0].ebuf[0][k];   // alpha_0 -> row 1
        sm->bat[1].aslab[0][KK + k] = sm->bat[1].ebuf[0][k];
    }

    for (int p = 0; p <= NCH; ++p) {
        const int pb = p & 1;

        if (isVal && p < NCH) {
            if (p > 0 && jh == 0) {   // carry alpha into row 0 of the new slab
                sm->bat[0].aslab[pb][k] = sm->bat[0].aslab[pb ^ 1][CHUNK * KK + k];
                sm->bat[1].aslab[pb][k] = sm->bat[1].aslab[pb ^ 1][CHUNK * KK + k];
            }
            asm volatile("bar.sync 1, 128;" ::: "memory");

            const int r0 = (p == 0) ? 1 : 0;
            for (int r = r0; r < CHUNK; ++r) {
                const float* s0 = sm->bat[0].aslab[pb] + r * KK + jh * 32;
                const float* s1 = sm->bat[1].aslab[pb] + r * KK + jh * 32;
                float emit0 = sm->bat[0].ebuf[pb][r * KK + k];
                float emit1 = sm->bat[1].ebuf[pb][r * KK + k];

                unsigned long long vp0[16], vp1[16];
#pragma unroll
                for (int i = 0; i < 8; ++i) {
                    ulonglong2 sv0 = ((const ulonglong2*)s0)[i];
                    ulonglong2 sv1 = ((const ulonglong2*)s1)[i];
                    vp0[2 * i]     = addx2(sv0.x, trp[2 * i]);
                    vp0[2 * i + 1] = addx2(sv0.y, trp[2 * i + 1]);
                    vp1[2 * i]     = addx2(sv1.x, trp[2 * i]);
                    vp1[2 * i + 1] = addx2(sv1.y, trp[2 * i + 1]);
                }
                float mx0[16], mx1[16];
#pragma unroll
                for (int i = 0; i < 16; ++i) {
                    mx0[i] = fmaxf(lo32(vp0[i]), hi32(vp0[i]));
                    mx1[i] = fmaxf(lo32(vp1[i]), hi32(vp1[i]));
                }
#pragma unroll
                for (int i = 0; i < 8; ++i) {
                    mx0[i] = fmaxf(mx0[2 * i], mx0[2 * i + 1]);
                    mx1[i] = fmaxf(mx1[2 * i], mx1[2 * i + 1]);
                }
#pragma unroll
                for (int i = 0; i < 4; ++i) {
                    mx0[i] = fmaxf(mx0[2 * i], mx0[2 * i + 1]);
                    mx1[i] = fmaxf(mx1[2 * i], mx1[2 * i + 1]);
                }
                float vmax0 = fmaxf(fmaxf(mx0[0], mx0[1]), fmaxf(mx0[2], mx0[3]));
                float vmax1 = fmaxf(fmaxf(mx1[0], mx1[1]), fmaxf(mx1[2], mx1[3]));

                float po0 = __shfl_xor_sync(0xffffffffu, vmax0, 1);
                float po1 = __shfl_xor_sync(0xffffffffu, vmax1, 1);
                float best0 = fmaxf(vmax0, po0);
                float best1 = fmaxf(vmax1, po1);

                if (jh == 0) {
                    sm->bat[0].bslab[pb][r * KK + k]       = best0;
                    sm->bat[0].aslab[pb][(r + 1) * KK + k] = best0 + emit0;
                    sm->bat[1].bslab[pb][r * KK + k]       = best1;
                    sm->bat[1].aslab[pb][(r + 1) * KK + k] = best1 + emit1;
                }
                asm volatile("bar.sync 1, 128;" ::: "memory");
            }

            if (p == NCH - 1 && stid == 0) {   // last tags
#pragma unroll
                for (int bb = 0; bb < NBAT; ++bb) {
                    const float* fin = sm->bat[bb].aslab[pb] + CHUNK * KK;
                    float bv = fin[0]; int bk = 0;
#pragma unroll
                    for (int kk = 1; kk < KK; ++kk) {
                        float vv = fin[kk];
                        if (vv > bv) { bv = vv; bk = kk; }
                    }
                    g_lasttag[b0 + bb] = bk;
                }
            }

            if (p + 1 < NCH) {   // prefetch chunk p+2 (both batches)
                if (p + 2 < NCH) {
                    uint32_t sn0 = (uint32_t)__cvta_generic_to_shared(sm->bat[0].ebuf[pb]);
                    uint32_t sn1 = (uint32_t)__cvta_generic_to_shared(sm->bat[1].ebuf[pb]);
                    const float* g0 = pb0 + (size_t)(p + 2) * CHUNK * KK;
                    const float* g1 = pb1 + (size_t)(p + 2) * CHUNK * KK;
#pragma unroll
                    for (int i = 0; i < 8; ++i) {
                        cpasync16(sn0 + (i * 128 + stid) * 16, g0 + (i * 128 + stid) * 4);
                        cpasync16(sn1 + (i * 128 + stid) * 16, g1 + (i * 128 + stid) * 4);
                    }
                }
                cpasync_commit();
                cpasync_wait1();   // chunk p+1 (both batches) resident
            }
        }

        if (!isVal && p >= 1) {   // bp for chunk q = p-1, own batch
            const int q  = p - 1;
            const int qb = q & 1;
            SmemB* sb = &sm->bat[bslice];
#pragma unroll 2
            for (int r = 0; r < CHUNK; ++r) {
                if (q == 0 && r == 0) {
                    if (jh == 0) sb->bps[qb][k] = (uint8_t)k;   // never applied
                    continue;
                }
                const float* arow = sb->aslab[qb] + r * KK + jh * 32;
                float bestv = sb->bslab[qb][r * KK + k];
                unsigned long long bestp = pk2(bestv, bestv);

                unsigned long long vp[16];
#pragma unroll
                for (int i = 0; i < 8; ++i) {
                    ulonglong2 sv = ((const ulonglong2*)arow)[i];
                    vp[2 * i]     = addx2(sv.x, trp[2 * i]);
                    vp[2 * i + 1] = addx2(sv.y, trp[2 * i + 1]);
                }
                float kf[16];
#pragma unroll
                for (int i = 0; i < 16; ++i) {
                    unsigned long long dp = fma2(vp[i], NEG1X2, bestp); // best - v >= +0
                    unsigned long long kp = fma2(dp, BIGX2, idxp[i]);   // j exact if d==0
                    kf[i] = fminf(lo32(kp), hi32(kp));
                }
#pragma unroll
                for (int i = 0; i < 8; ++i) kf[i] = fminf(kf[2 * i], kf[2 * i + 1]);
#pragma unroll
                for (int i = 0; i < 4; ++i) kf[i] = fminf(kf[2 * i], kf[2 * i + 1]);
                float kmin = fminf(fminf(kf[0], kf[1]), fminf(kf[2], kf[3]));
                float pk   = __shfl_xor_sync(0xffffffffu, kmin, 1);
                kmin = fminf(kmin, pk);

                if (jh == 0) sb->bps[qb][r * KK + k] = (uint8_t)(int)kmin;
            }
            // batch-group sync, then flush this batch's 4 KB of bps
            asm volatile("bar.sync %0, 128;" :: "r"(2 + bslice) : "memory");
            {
                uint4* dst = (uint4*)(g_bp + (size_t)(b0 + bslice) * TT * KK +
                                      (size_t)q * CHUNK * KK);
                const uint4* src = (const uint4*)sb->bps[qb];
                dst[stid]       = src[stid];
                dst[stid + 128] = src[stid + 128];
            }
        }
        __syncthreads();   // chunk handoff
    }
}

// =====================================================================
// Backward: serial walk per batch through shared reloads + lengths.
// =====================================================================
__global__ __launch_bounds__(128) void bwd_kernel(const int* __restrict__ mask,
                                                  float* __restrict__ out) {
    const int b   = blockIdx.x;
    const int tid = threadIdx.x;

    __shared__ __align__(16) uint8_t wb[GRP][CHUNK][KK];   // 32 KB
    __shared__ __align__(16) float   tagseg[GRP * CHUNK];
    __shared__ int scur;

    if (tid == 0) scur = g_lasttag[b];

    const uint8_t* bpb = g_bp + (size_t)b * TT * KK;
    for (int base = NCH - GRP; base >= 0; base -= GRP) {
        const uint4* src = (const uint4*)(bpb + (size_t)base * CHUNK * KK);
        uint4* dst = (uint4*)wb;
#pragma unroll
        for (int i = 0; i < (GRP * CHUNK * KK / 16) / 128; ++i)
            dst[tid + 128 * i] = src[tid + 128 * i];
        __syncthreads();

        if (tid == 0) {
            int cur = scur;                 // tag at t = 64*(base+GRP) - 1
            for (int g = GRP - 1; g >= 0; --g) {
                tagseg[g * CHUNK + CHUNK - 1] = (float)cur;
                for (int r = CHUNK - 1; r >= 1; --r) {
                    cur = wb[g][r][cur];
                    tagseg[g * CHUNK + r - 1] = (float)cur;
                }
                cur = wb[g][0][cur];        // cross chunk boundary
            }
            scur = cur;
        }
        __syncthreads();

        float* ob = out + (size_t)b * TT + base * CHUNK;
#pragma unroll
        for (int i = 0; i < (GRP * CHUNK) / 128; ++i)
            ob[tid + 128 * i] = tagseg[tid + 128 * i];
        __syncthreads();
    }

    // sequence length
    {
        int s = 0;
        const int4* m = (const int4*)(mask + (size_t)b * TT);
        for (int i = tid; i < TT / 4; i += 128) {
            int4 v = m[i];
            s += v.x + v.y + v.z + v.w;
        }
#pragma unroll
        for (int off = 16; off; off >>= 1) s += __shfl_xor_sync(0xffffffffu, s, off);
        __shared__ int red[4];
        if ((tid & 31) == 0) red[tid >> 5] = s;
        __syncthreads();
        if (tid == 0)
            out[(size_t)BB * TT + b] = (float)(red[0] + red[1] + red[2] + red[3]);
    }
}

// =====================================================================
extern "C" void kernel_launch(void* const* d_in, const int* in_sizes, int n_in,
                              void* d_out, int out_size) {
    const float* pot   = nullptr;
    const float* trans = nullptr;
    const int*   mask  = nullptr;
    for (int i = 0; i < n_in; ++i) {
        if      (in_sizes[i] == BB * TT * KK) pot   = (const float*)d_in[i];
        else if (in_sizes[i] == KK * KK)      trans = (const float*)d_in[i];
        else if (in_sizes[i] == BB * TT)      mask  = (const int*)  d_in[i];
    }
    float* out = (float*)d_out;   // [tags (128*4096) | lengths (128)] as f32

    cudaFuncSetAttribute(fwd_kernel, cudaFuncAttributeMaxDynamicSharedMemorySize,
                         (int)sizeof(Smem));
    fwd_kernel<<<BB / NBAT, 384, sizeof(Smem)>>>(pot, trans);
    bwd_kernel<<<BB, 128>>>(mask, out);
}

// round 14
// speedup vs baseline: 2.0813x; 2.0813x over previous
#include <cuda_runtime.h>
#include <cstdint>

#define BB 128
#define TT 4096
#define KK 64
#define CHUNK 64
#define NCH   (TT / CHUNK)   /* 64 chunks */
#define GRP   8              /* chunks per backward group (32 KB) */

// scratch (static __device__: allocation-free)
__device__ __align__(16) uint8_t g_bp[(size_t)BB * TT * KK];   // 32 MB backpointers
__device__ int g_lasttag[BB];

// dynamic smem
struct Smem {
    float   ebuf[2][CHUNK * KK];         // 32 KB emission double buffer
    float   aslab[2][(CHUNK + 1) * KK];  // 32.5 KB alpha rows (row 0 = carry-in)
    float   bslab[2][CHUNK * KK];        // 32 KB per-step pre-emission max
    uint8_t bps[2][CHUNK * KK];          // 8 KB bp staging
};

__device__ __forceinline__ void cpasync16(uint32_t saddr, const void* gptr) {
    asm volatile("cp.async.ca.shared.global [%0], [%1], 16;" :: "r"(saddr), "l"(gptr));
}
__device__ __forceinline__ void cpasync_commit() { asm volatile("cp.async.commit_group;"); }
__device__ __forceinline__ void cpasync_wait1()  { asm volatile("cp.async.wait_group 1;"); }

__device__ __forceinline__ unsigned long long addx2(unsigned long long a, unsigned long long b) {
    unsigned long long d;
    asm("add.rn.f32x2 %0, %1, %2;" : "=l"(d) : "l"(a), "l"(b));
    return d;
}
__device__ __forceinline__ unsigned long long fma2(unsigned long long a, unsigned long long b,
                                                   unsigned long long c) {
    unsigned long long d;
    asm("fma.rn.f32x2 %0, %1, %2, %3;" : "=l"(d) : "l"(a), "l"(b), "l"(c));
    return d;
}
__device__ __forceinline__ float lo32(unsigned long long x) { return __uint_as_float((unsigned)x); }
__device__ __forceinline__ float hi32(unsigned long long x) { return __uint_as_float((unsigned)(x >> 32)); }
__device__ __forceinline__ unsigned long long pk2(float a, float b) {
    return (unsigned long long)__float_as_uint(a) | ((unsigned long long)__float_as_uint(b) << 32);
}

#define NEG1X2 0xBF800000BF800000ULL   /* (-1, -1) */
#define BIGX2  0x5F0000005F000000ULL   /* (2^63, 2^63) */
#define TWO2   0x4000000040000000ULL   /* ( 2,  2) */
#define IDX01  0x3F80000000000000ULL   /* ( 0,  1) */

// =====================================================================
// Warp-specialized forward, SMSP-balanced.
//  VALUE = warps 0-1 (64 threads, SMSP 0,1): thread k reduces ALL 64
//    preds (no shuffle merge); bar.sync 1,64 per step.
//  BP = warps 2-11 (10 warps): warp handles one k-half of its assigned
//    rows; weighted row counts put most bp work on SMSP 2,3 (which have
//    no chain warps). Each lane covers a full row for its k.
// Exact: identical add.rn.f32x2; d = RN(best-v) == +0 iff winner;
// key = RN(d*2^63 + j) == j for winners; min-key = first-index argmax.
// =====================================================================
__global__ void __launch_bounds__(384, 1) fwd_kernel(const float* __restrict__ pot,
                                                     const float* __restrict__ trans) {
    extern __shared__ char smraw[];
    Smem* sm = (Smem*)smraw;

    const int b    = blockIdx.x;
    const int tid  = threadIdx.x;
    const int lane = tid & 31;
    const int wid  = tid >> 5;
    const bool isVal = (tid < 64);

    int k;
    if (isVal) k = tid;
    else       k = lane + (((wid - 2) & 1) ? 32 : 0);

    // transitions column k, packed pairs over j
    unsigned long long trp[32];
#pragma unroll
    for (int i = 0; i < 32; ++i)
        trp[i] = pk2(trans[(2 * i) * KK + k], trans[(2 * i + 1) * KK + k]);

    // bp row ranges per warp-pair: heavy pairs live on SMSP 2,3
    int rstart = 0, rcnt = 0;
    if (!isVal) {
        int pi = (wid - 2) >> 1;      // 0..4
        if      (pi == 0) { rstart = 0;  rcnt = 17; }   // w2,w3   SMSP 2,3
        else if (pi == 1) { rstart = 17; rcnt = 6;  }   // w4,w5   SMSP 0,1
        else if (pi == 2) { rstart = 23; rcnt = 17; }   // w6,w7   SMSP 2,3
        else if (pi == 3) { rstart = 40; rcnt = 6;  }   // w8,w9   SMSP 0,1
        else              { rstart = 46; rcnt = 18; }   // w10,w11 SMSP 2,3
    }

    const float* pbm = pot + (size_t)b * TT * KK;

    if (isVal) {   // prologue: prefetch emission chunks 0, 1 (64 threads)
        uint32_t s0 = (uint32_t)__cvta_generic_to_shared(sm->ebuf[0]);
        uint32_t s1 = (uint32_t)__cvta_generic_to_shared(sm->ebuf[1]);
#pragma unroll
        for (int i = 0; i < 16; ++i)
            cpasync16(s0 + (i * 64 + tid) * 16, pbm + (i * 64 + tid) * 4);
        cpasync_commit();
#pragma unroll
        for (int i = 0; i < 16; ++i)
            cpasync16(s1 + (i * 64 + tid) * 16, pbm + CHUNK * KK + (i * 64 + tid) * 4);
        cpasync_commit();
        cpasync_wait1();
    }
    __syncthreads();
    if (isVal)
        sm->aslab[0][KK + k] = sm->ebuf[0][k];   // alpha_0 -> chunk0 row 1

    for (int p = 0; p <= NCH; ++p) {
        const int pb = p & 1;

        if (isVal && p < NCH) {
            if (p > 0)   // carry alpha_{p*64-1} into row 0 of the new slab
                sm->aslab[pb][k] = sm->aslab[pb ^ 1][CHUNK * KK + k];
            asm volatile("bar.sync 1, 64;" ::: "memory");

            const int r0 = (p == 0) ? 1 : 0;
            for (int r = r0; r < CHUNK; ++r) {
                const ulonglong2* arow = (const ulonglong2*)(sm->aslab[pb] + r * KK);
                float emit = sm->ebuf[pb][r * KK + k];

                float gm[4];
#pragma unroll
                for (int g = 0; g < 4; ++g) {
                    ulonglong2 s0 = arow[4 * g + 0], s1 = arow[4 * g + 1];
                    ulonglong2 s2 = arow[4 * g + 2], s3 = arow[4 * g + 3];
                    unsigned long long v0 = addx2(s0.x, trp[8 * g + 0]);
                    unsigned long long v1 = addx2(s0.y, trp[8 * g + 1]);
                    unsigned long long v2 = addx2(s1.x, trp[8 * g + 2]);
                    unsigned long long v3 = addx2(s1.y, trp[8 * g + 3]);
                    unsigned long long v4 = addx2(s2.x, trp[8 * g + 4]);
                    unsigned long long v5 = addx2(s2.y, trp[8 * g + 5]);
                    unsigned long long v6 = addx2(s3.x, trp[8 * g + 6]);
                    unsigned long long v7 = addx2(s3.y, trp[8 * g + 7]);
                    float m0 = fmaxf(lo32(v0), hi32(v0));
                    float m1 = fmaxf(lo32(v1), hi32(v1));
                    float m2 = fmaxf(lo32(v2), hi32(v2));
                    float m3 = fmaxf(lo32(v3), hi32(v3));
                    float m4 = fmaxf(lo32(v4), hi32(v4));
                    float m5 = fmaxf(lo32(v5), hi32(v5));
                    float m6 = fmaxf(lo32(v6), hi32(v6));
                    float m7 = fmaxf(lo32(v7), hi32(v7));
                    m0 = fmaxf(m0, m1); m2 = fmaxf(m2, m3);
                    m4 = fmaxf(m4, m5); m6 = fmaxf(m6, m7);
                    gm[g] = fmaxf(fmaxf(m0, m2), fmaxf(m4, m6));
                }
                float best = fmaxf(fmaxf(gm[0], gm[1]), fmaxf(gm[2], gm[3]));

                sm->bslab[pb][r * KK + k]       = best;
                sm->aslab[pb][(r + 1) * KK + k] = best + emit;
                asm volatile("bar.sync 1, 64;" ::: "memory");
            }

            if (p == NCH - 1 && tid == 0) {   // last tag
                const float* fin = sm->aslab[pb] + CHUNK * KK;
                float bv = fin[0]; int bk = 0;
#pragma unroll
                for (int kk = 1; kk < KK; ++kk) {
                    float vv = fin[kk];
                    if (vv > bv) { bv = vv; bk = kk; }
                }
                g_lasttag[b] = bk;
            }

            if (p + 1 < NCH) {   // prefetch chunk p+2 into freed ebuf[pb]
                if (p + 2 < NCH) {
                    uint32_t sn = (uint32_t)__cvta_generic_to_shared(sm->ebuf[pb]);
                    const float* gsrc = pbm + (size_t)(p + 2) * CHUNK * KK;
#pragma unroll
                    for (int i = 0; i < 16; ++i)
                        cpasync16(sn + (i * 64 + tid) * 16, gsrc + (i * 64 + tid) * 4);
                }
                cpasync_commit();
                cpasync_wait1();   // chunk p+1 resident
            }
        }

        if (!isVal && p >= 1) {   // bp for chunk q = p-1 (slabs stable)
            const int q  = p - 1;
            const int qb = q & 1;

            for (int rr = 0; rr < rcnt; ++rr) {
                const int r = rstart + rr;
                if (q == 0 && r == 0) {
                    sm->bps[qb][k] = (uint8_t)k;   // placeholder (never applied)
                    continue;
                }
                const ulonglong2* arow = (const ulonglong2*)(sm->aslab[qb] + r * KK);
                float bestv = sm->bslab[qb][r * KK + k];
                unsigned long long bestp = pk2(bestv, bestv);
                unsigned long long idxc  = IDX01;   // (j, j+1) running pair

                float km[4];
#pragma unroll
                for (int g = 0; g < 4; ++g) {
                    ulonglong2 s0 = arow[4 * g + 0], s1 = arow[4 * g + 1];
                    ulonglong2 s2 = arow[4 * g + 2], s3 = arow[4 * g + 3];
                    unsigned long long vv[8];
                    vv[0] = addx2(s0.x, trp[8 * g + 0]);
                    vv[1] = addx2(s0.y, trp[8 * g + 1]);
                    vv[2] = addx2(s1.x, trp[8 * g + 2]);
                    vv[3] = addx2(s1.y, trp[8 * g + 3]);
                    vv[4] = addx2(s2.x, trp[8 * g + 4]);
                    vv[5] = addx2(s2.y, trp[8 * g + 5]);
                    vv[6] = addx2(s3.x, trp[8 * g + 6]);
                    vv[7] = addx2(s3.y, trp[8 * g + 7]);
                    float f[8];
#pragma unroll
                    for (int i = 0; i < 8; ++i) {
                        unsigned long long dp = fma2(vv[i], NEG1X2, bestp); // best - v
                        unsigned long long kp = fma2(dp, BIGX2, idxc);      // j if d==0
                        idxc = addx2(idxc, TWO2);
                        f[i] = fminf(lo32(kp), hi32(kp));
                    }
                    f[0] = fminf(f[0], f[1]); f[2] = fminf(f[2], f[3]);
                    f[4] = fminf(f[4], f[5]); f[6] = fminf(f[6], f[7]);
                    km[g] = fminf(fminf(f[0], f[2]), fminf(f[4], f[6]));
                }
                float kmin = fminf(fminf(km[0], km[1]), fminf(km[2], km[3]));
                sm->bps[qb][r * KK + k] = (uint8_t)(int)kmin;
            }

            // bp-group barrier, then cooperative 4 KB flush to global
            asm volatile("bar.sync 2, 320;" ::: "memory");
            {
                const int bpt = tid - 64;   // 0..319
                if (bpt < 256) {
                    uint4* dst = (uint4*)(g_bp + (size_t)b * TT * KK +
                                          (size_t)q * CHUNK * KK);
                    dst[bpt] = ((const uint4*)sm->bps[qb])[bpt];
                }
            }
        }
        __syncthreads();   // chunk handoff
    }
}

// =====================================================================
// Backward: serial walk per batch through shared reloads + lengths.
// =====================================================================
__global__ __launch_bounds__(128) void bwd_kernel(const int* __restrict__ mask,
                                                  float* __restrict__ out) {
    const int b   = blockIdx.x;
    const int tid = threadIdx.x;

    __shared__ __align__(16) uint8_t wb[GRP][CHUNK][KK];   // 32 KB
    __shared__ __align__(16) float   tagseg[GRP * CHUNK];
    __shared__ int scur;

    if (tid == 0) scur = g_lasttag[b];

    const uint8_t* bpb = g_bp + (size_t)b * TT * KK;
    for (int base = NCH - GRP; base >= 0; base -= GRP) {
        const uint4* src = (const uint4*)(bpb + (size_t)base * CHUNK * KK);
        uint4* dst = (uint4*)wb;
#pragma unroll
        for (int i = 0; i < (GRP * CHUNK * KK / 16) / 128; ++i)
            dst[tid + 128 * i] = src[tid + 128 * i];
        __syncthreads();

        if (tid == 0) {
            int cur = scur;                 // tag at t = 64*(base+GRP) - 1
            for (int g = GRP - 1; g >= 0; --g) {
                tagseg[g * CHUNK + CHUNK - 1] = (float)cur;
                for (int r = CHUNK - 1; r >= 1; --r) {
                    cur = wb[g][r][cur];
                    tagseg[g * CHUNK + r - 1] = (float)cur;
                }
                cur = wb[g][0][cur];        // cross chunk boundary
            }
            scur = cur;
        }
        __syncthreads();

        float* ob = out + (size_t)b * TT + base * CHUNK;
#pragma unroll
        for (int i = 0; i < (GRP * CHUNK) / 128; ++i)
            ob[tid + 128 * i] = tagseg[tid + 128 * i];
        __syncthreads();
    }

    // sequence length
    {
        int s = 0;
        const int4* m = (const int4*)(mask + (size_t)b * TT);
        for (int i = tid; i < TT / 4; i += 128) {
            int4 v = m[i];
            s += v.x + v.y + v.z + v.w;
        }
#pragma unroll
        for (int off = 16; off; off >>= 1) s += __shfl_xor_sync(0xffffffffu, s, off);
        __shared__ int red[4];
        if ((tid & 31) == 0) red[tid >> 5] = s;
        __syncthreads();
        if (tid == 0)
            out[(size_t)BB * TT + b] = (float)(red[0] + red[1] + red[2] + red[3]);
    }
}

// =====================================================================
extern "C" void kernel_launch(void* const* d_in, const int* in_sizes, int n_in,
                              void* d_out, int out_size) {
    const float* pot   = nullptr;
    const float* trans = nullptr;
    const int*   mask  = nullptr;
    for (int i = 0; i < n_in; ++i) {
        if      (in_sizes[i] == BB * TT * KK) pot   = (const float*)d_in[i];
        else if (in_sizes[i] == KK * KK)      trans = (const float*)d_in[i];
        else if (in_sizes[i] == BB * TT)      mask  = (const int*)  d_in[i];
    }
    float* out = (float*)d_out;   // [tags (128*4096) | lengths (128)] as f32

    cudaFuncSetAttribute(fwd_kernel, cudaFuncAttributeMaxDynamicSharedMemorySize,
                         (int)sizeof(Smem));
    fwd_kernel<<<BB, 384, sizeof(Smem)>>>(pot, trans);
    bwd_kernel<<<BB, 128>>>(mask, out);
}

// round 15
// speedup vs baseline: 2.2975x; 1.1039x over previous
#include <cuda_runtime.h>
#include <cstdint>

#define BB 128
#define TT 4096
#define KK 64
#define CHUNK 64
#define NCH   (TT / CHUNK)   /* 64 chunks */

// scratch (static __device__: allocation-free)
__device__ __align__(16) uint8_t g_bp[(size_t)BB * TT * KK];   // 32 MB backpointers
__device__ int g_lasttag[BB];

// dynamic smem (forward)
struct Smem {
    float   ebuf[2][CHUNK * KK];         // 32 KB emission double buffer
    float   aslab[2][(CHUNK + 1) * KK];  // 32.5 KB alpha rows (row 0 = carry-in)
    float   bslab[2][CHUNK * KK];        // 32 KB per-step pre-emission max
    uint8_t bps[2][CHUNK * KK];          // 8 KB bp staging
};

__device__ __forceinline__ void cpasync16(uint32_t saddr, const void* gptr) {
    asm volatile("cp.async.ca.shared.global [%0], [%1], 16;" :: "r"(saddr), "l"(gptr));
}
__device__ __forceinline__ void cpasync_commit() { asm volatile("cp.async.commit_group;"); }
__device__ __forceinline__ void cpasync_wait1()  { asm volatile("cp.async.wait_group 1;"); }

__device__ __forceinline__ unsigned long long addx2(unsigned long long a, unsigned long long b) {
    unsigned long long d;
    asm("add.rn.f32x2 %0, %1, %2;" : "=l"(d) : "l"(a), "l"(b));
    return d;
}
__device__ __forceinline__ unsigned long long fma2(unsigned long long a, unsigned long long b,
                                                   unsigned long long c) {
    unsigned long long d;
    asm("fma.rn.f32x2 %0, %1, %2, %3;" : "=l"(d) : "l"(a), "l"(b), "l"(c));
    return d;
}
__device__ __forceinline__ float lo32(unsigned long long x) { return __uint_as_float((unsigned)x); }
__device__ __forceinline__ float hi32(unsigned long long x) { return __uint_as_float((unsigned)(x >> 32)); }
__device__ __forceinline__ unsigned long long pk2(float a, float b) {
    return (unsigned long long)__float_as_uint(a) | ((unsigned long long)__float_as_uint(b) << 32);
}

#define NEG1X2 0xBF800000BF800000ULL   /* (-1, -1) */
#define BIGX2  0x5F0000005F000000ULL   /* (2^63, 2^63) */
#define TWO2   0x4000000040000000ULL   /* ( 2,  2) */
#define IDX01  0x3F80000000000000ULL   /* ( 0,  1) */

// =====================================================================
// Forward (UNCHANGED from R14, passing at 578 us).
// VALUE = warps 0-1 (64 threads): thread k reduces all 64 preds.
// BP = warps 2-11: float-key first-index argmax, heavy rows on SMSP 2,3.
// =====================================================================
__global__ void __launch_bounds__(384, 1) fwd_kernel(const float* __restrict__ pot,
                                                     const float* __restrict__ trans) {
    extern __shared__ char smraw[];
    Smem* sm = (Smem*)smraw;

    const int b    = blockIdx.x;
    const int tid  = threadIdx.x;
    const int lane = tid & 31;
    const int wid  = tid >> 5;
    const bool isVal = (tid < 64);

    int k;
    if (isVal) k = tid;
    else       k = lane + (((wid - 2) & 1) ? 32 : 0);

    unsigned long long trp[32];
#pragma unroll
    for (int i = 0; i < 32; ++i)
        trp[i] = pk2(trans[(2 * i) * KK + k], trans[(2 * i + 1) * KK + k]);

    int rstart = 0, rcnt = 0;
    if (!isVal) {
        int pi = (wid - 2) >> 1;
        if      (pi == 0) { rstart = 0;  rcnt = 17; }
        else if (pi == 1) { rstart = 17; rcnt = 6;  }
        else if (pi == 2) { rstart = 23; rcnt = 17; }
        else if (pi == 3) { rstart = 40; rcnt = 6;  }
        else              { rstart = 46; rcnt = 18; }
    }

    const float* pbm = pot + (size_t)b * TT * KK;

    if (isVal) {
        uint32_t s0 = (uint32_t)__cvta_generic_to_shared(sm->ebuf[0]);
        uint32_t s1 = (uint32_t)__cvta_generic_to_shared(sm->ebuf[1]);
#pragma unroll
        for (int i = 0; i < 16; ++i)
            cpasync16(s0 + (i * 64 + tid) * 16, pbm + (i * 64 + tid) * 4);
        cpasync_commit();
#pragma unroll
        for (int i = 0; i < 16; ++i)
            cpasync16(s1 + (i * 64 + tid) * 16, pbm + CHUNK * KK + (i * 64 + tid) * 4);
        cpasync_commit();
        cpasync_wait1();
    }
    __syncthreads();
    if (isVal)
        sm->aslab[0][KK + k] = sm->ebuf[0][k];

    for (int p = 0; p <= NCH; ++p) {
        const int pb = p & 1;

        if (isVal && p < NCH) {
            if (p > 0)
                sm->aslab[pb][k] = sm->aslab[pb ^ 1][CHUNK * KK + k];
            asm volatile("bar.sync 1, 64;" ::: "memory");

            const int r0 = (p == 0) ? 1 : 0;
            for (int r = r0; r < CHUNK; ++r) {
                const ulonglong2* arow = (const ulonglong2*)(sm->aslab[pb] + r * KK);
                float emit = sm->ebuf[pb][r * KK + k];

                float gm[4];
#pragma unroll
                for (int g = 0; g < 4; ++g) {
                    ulonglong2 s0 = arow[4 * g + 0], s1 = arow[4 * g + 1];
                    ulonglong2 s2 = arow[4 * g + 2], s3 = arow[4 * g + 3];
                    unsigned long long v0 = addx2(s0.x, trp[8 * g + 0]);
                    unsigned long long v1 = addx2(s0.y, trp[8 * g + 1]);
                    unsigned long long v2 = addx2(s1.x, trp[8 * g + 2]);
                    unsigned long long v3 = addx2(s1.y, trp[8 * g + 3]);
                    unsigned long long v4 = addx2(s2.x, trp[8 * g + 4]);
                    unsigned long long v5 = addx2(s2.y, trp[8 * g + 5]);
                    unsigned long long v6 = addx2(s3.x, trp[8 * g + 6]);
                    unsigned long long v7 = addx2(s3.y, trp[8 * g + 7]);
                    float m0 = fmaxf(lo32(v0), hi32(v0));
                    float m1 = fmaxf(lo32(v1), hi32(v1));
                    float m2 = fmaxf(lo32(v2), hi32(v2));
                    float m3 = fmaxf(lo32(v3), hi32(v3));
                    float m4 = fmaxf(lo32(v4), hi32(v4));
                    float m5 = fmaxf(lo32(v5), hi32(v5));
                    float m6 = fmaxf(lo32(v6), hi32(v6));
                    float m7 = fmaxf(lo32(v7), hi32(v7));
                    m0 = fmaxf(m0, m1); m2 = fmaxf(m2, m3);
                    m4 = fmaxf(m4, m5); m6 = fmaxf(m6, m7);
                    gm[g] = fmaxf(fmaxf(m0, m2), fmaxf(m4, m6));
                }
                float best = fmaxf(fmaxf(gm[0], gm[1]), fmaxf(gm[2], gm[3]));

                sm->bslab[pb][r * KK + k]       = best;
                sm->aslab[pb][(r + 1) * KK + k] = best + emit;
                asm volatile("bar.sync 1, 64;" ::: "memory");
            }

            if (p == NCH - 1 && tid == 0) {
                const float* fin = sm->aslab[pb] + CHUNK * KK;
                float bv = fin[0]; int bk = 0;
#pragma unroll
                for (int kk = 1; kk < KK; ++kk) {
                    float vv = fin[kk];
                    if (vv > bv) { bv = vv; bk = kk; }
                }
                g_lasttag[b] = bk;
            }

            if (p + 1 < NCH) {
                if (p + 2 < NCH) {
                    uint32_t sn = (uint32_t)__cvta_generic_to_shared(sm->ebuf[pb]);
                    const float* gsrc = pbm + (size_t)(p + 2) * CHUNK * KK;
#pragma unroll
                    for (int i = 0; i < 16; ++i)
                        cpasync16(sn + (i * 64 + tid) * 16, gsrc + (i * 64 + tid) * 4);
                }
                cpasync_commit();
                cpasync_wait1();
            }
        }

        if (!isVal && p >= 1) {
            const int q  = p - 1;
            const int qb = q & 1;

            for (int rr = 0; rr < rcnt; ++rr) {
                const int r = rstart + rr;
                if (q == 0 && r == 0) {
                    sm->bps[qb][k] = (uint8_t)k;
                    continue;
                }
                const ulonglong2* arow = (const ulonglong2*)(sm->aslab[qb] + r * KK);
                float bestv = sm->bslab[qb][r * KK + k];
                unsigned long long bestp = pk2(bestv, bestv);
                unsigned long long idxc  = IDX01;

                float km[4];
#pragma unroll
                for (int g = 0; g < 4; ++g) {
                    ulonglong2 s0 = arow[4 * g + 0], s1 = arow[4 * g + 1];
                    ulonglong2 s2 = arow[4 * g + 2], s3 = arow[4 * g + 3];
                    unsigned long long vv[8];
                    vv[0] = addx2(s0.x, trp[8 * g + 0]);
                    vv[1] = addx2(s0.y, trp[8 * g + 1]);
                    vv[2] = addx2(s1.x, trp[8 * g + 2]);
                    vv[3] = addx2(s1.y, trp[8 * g + 3]);
                    vv[4] = addx2(s2.x, trp[8 * g + 4]);
                    vv[5] = addx2(s2.y, trp[8 * g + 5]);
                    vv[6] = addx2(s3.x, trp[8 * g + 6]);
                    vv[7] = addx2(s3.y, trp[8 * g + 7]);
                    float f[8];
#pragma unroll
                    for (int i = 0; i < 8; ++i) {
                        unsigned long long dp = fma2(vv[i], NEG1X2, bestp);
                        unsigned long long kp = fma2(dp, BIGX2, idxc);
                        idxc = addx2(idxc, TWO2);
                        f[i] = fminf(lo32(kp), hi32(kp));
                    }
                    f[0] = fminf(f[0], f[1]); f[2] = fminf(f[2], f[3]);
                    f[4] = fminf(f[4], f[5]); f[6] = fminf(f[6], f[7]);
                    km[g] = fminf(fminf(f[0], f[2]), fminf(f[4], f[6]));
                }
                float kmin = fminf(fminf(km[0], km[1]), fminf(km[2], km[3]));
                sm->bps[qb][r * KK + k] = (uint8_t)(int)kmin;
            }

            asm volatile("bar.sync 2, 320;" ::: "memory");
            {
                const int bpt = tid - 64;
                if (bpt < 256) {
                    uint4* dst = (uint4*)(g_bp + (size_t)b * TT * KK +
                                          (size_t)q * CHUNK * KK);
                    dst[bpt] = ((const uint4*)sm->bps[qb])[bpt];
                }
            }
        }
        __syncthreads();
    }
}

// =====================================================================
// Parallel backward: compose chunk maps (warp-parallel) -> boundary
// chase (63 hops) -> warp-parallel chunk walks -> lengths.
// F_c maps tag@(64c+63) -> tag@(64c-1);  btag[c-1] = F_c[btag[c]].
// =====================================================================
__global__ __launch_bounds__(256) void bwd_kernel(const int* __restrict__ mask,
                                                  float* __restrict__ out) {
    const int b    = blockIdx.x;
    const int tid  = threadIdx.x;
    const int wid  = tid >> 5;
    const int lane = tid & 31;

    __shared__ __align__(16) uint8_t cbuf[8][CHUNK * KK];  // 32 KB chunk buffers
    __shared__ __align__(16) uint8_t maps[NCH * KK];       // 4 KB composed maps
    __shared__ int   btag[NCH];
    __shared__ float tagbuf[8][CHUNK];

    const uint8_t* bpb = g_bp + (size_t)b * TT * KK;

    // ---- Phase A: compose 8 chunks per warp ----
    for (int i = 0; i < 8; ++i) {
        const int c = wid * 8 + i;
        const uint4* src = (const uint4*)(bpb + (size_t)c * CHUNK * KK);
        uint4* dst = (uint4*)cbuf[wid];
#pragma unroll
        for (int j = 0; j < 8; ++j) dst[lane + 32 * j] = src[lane + 32 * j];
        __syncwarp();

        int f0 = 2 * lane, f1 = 2 * lane + 1;   // identity seeds
#pragma unroll 4
        for (int r = CHUNK - 1; r >= 0; --r) {  // F = row0 o row1 o ... o row63
            const uint8_t* row = cbuf[wid] + r * KK;
            f0 = row[f0];
            f1 = row[f1];
        }
        *(uint16_t*)(maps + c * KK + 2 * lane) = (uint16_t)(f0 | (f1 << 8));
        __syncwarp();   // all chases done before buffer reuse
    }
    __syncthreads();

    // ---- Phase B: boundary chase ----
    if (tid == 0) {
        int cur = g_lasttag[b];
        btag[NCH - 1] = cur;
        for (int c = NCH - 1; c >= 1; --c) {
            cur = maps[c * KK + cur];     // tag@(64c-1) = tag@(64(c-1)+63)
            btag[c - 1] = cur;
        }
    }
    __syncthreads();

    // ---- Phase C: parallel chunk walks ----
    for (int i = 0; i < 8; ++i) {
        const int c = wid * 8 + i;
        const uint4* src = (const uint4*)(bpb + (size_t)c * CHUNK * KK);
        uint4* dst = (uint4*)cbuf[wid];
#pragma unroll
        for (int j = 0; j < 8; ++j) dst[lane + 32 * j] = src[lane + 32 * j];
        __syncwarp();

        if (lane == 0) {
            int cur = btag[c];                    // tag at t = 64c+63
            tagbuf[wid][CHUNK - 1] = (float)cur;
            for (int r = CHUNK - 1; r >= 1; --r) {
                cur = cbuf[wid][r * KK + cur];    // tag[t-1] = bp_t[tag_t]
                tagbuf[wid][r - 1] = (float)cur;
            }
        }
        __syncwarp();

        float2 o;
        o.x = tagbuf[wid][2 * lane];
        o.y = tagbuf[wid][2 * lane + 1];
        *(float2*)(out + (size_t)b * TT + c * CHUNK + 2 * lane) = o;
        __syncwarp();   // tag reads done before tagbuf/cbuf reuse
    }

    // ---- Phase D: sequence length ----
    {
        int s = 0;
        const int4* m = (const int4*)(mask + (size_t)b * TT);
        for (int i = tid; i < TT / 4; i += 256) {
            int4 v = m[i];
            s += v.x + v.y + v.z + v.w;
        }
#pragma unroll
        for (int off = 16; off; off >>= 1) s += __shfl_xor_sync(0xffffffffu, s, off);
        __shared__ int red[8];
        if ((tid & 31) == 0) red[tid >> 5] = s;
        __syncthreads();
        if (tid == 0) {
            int tot = 0;
#pragma unroll
            for (int i = 0; i < 8; ++i) tot += red[i];
            out[(size_t)BB * TT + b] = (float)tot;
        }
    }
}

// =====================================================================
extern "C" void kernel_launch(void* const* d_in, const int* in_sizes, int n_in,
                              void* d_out, int out_size) {
    const float* pot   = nullptr;
    const float* trans = nullptr;
    const int*   mask  = nullptr;
    for (int i = 0; i < n_in; ++i) {
        if      (in_sizes[i] == BB * TT * KK) pot   = (const float*)d_in[i];
        else if (in_sizes[i] == KK * KK)      trans = (const float*)d_in[i];
        else if (in_sizes[i] == BB * TT)      mask  = (const int*)  d_in[i];
    }
    float* out = (float*)d_out;   // [tags (128*4096) | lengths (128)] as f32

    cudaFuncSetAttribute(fwd_kernel, cudaFuncAttributeMaxDynamicSharedMemorySize,
                         (int)sizeof(Smem));
    fwd_kernel<<<BB, 384, sizeof(Smem)>>>(pot, trans);
    bwd_kernel<<<BB, 256>>>(mask, out);
}

// round 16
// speedup vs baseline: 2.4073x; 1.0478x over previous
#include <cuda_runtime.h>
#include <cstdint>

#define BB 128
#define TT 4096
#define KK 64
#define CHUNK 64
#define NCH   (TT / CHUNK)   /* 64 chunks */

// scratch (static __device__: allocation-free)
__device__ __align__(16) uint8_t g_bp[(size_t)BB * TT * KK];   // 32 MB backpointers
__device__ int g_lasttag[BB];

// dynamic smem (forward)
struct Smem {
    float   ebuf[2][CHUNK * KK];         // 32 KB emission double buffer
    float   aslab[2][(CHUNK + 1) * KK];  // 32.5 KB alpha rows (row 0 = carry-in)
    float   bslab[2][CHUNK * KK];        // 32 KB per-step pre-emission max
    uint8_t bps[2][CHUNK * KK];          // 8 KB bp staging
};

__device__ __forceinline__ void cpasync16(uint32_t saddr, const void* gptr) {
    asm volatile("cp.async.ca.shared.global [%0], [%1], 16;" :: "r"(saddr), "l"(gptr));
}
__device__ __forceinline__ void cpasync_commit() { asm volatile("cp.async.commit_group;"); }
__device__ __forceinline__ void cpasync_wait1()  { asm volatile("cp.async.wait_group 1;"); }

__device__ __forceinline__ unsigned long long addx2(unsigned long long a, unsigned long long b) {
    unsigned long long d;
    asm("add.rn.f32x2 %0, %1, %2;" : "=l"(d) : "l"(a), "l"(b));
    return d;
}
__device__ __forceinline__ unsigned long long fma2(unsigned long long a, unsigned long long b,
                                                   unsigned long long c) {
    unsigned long long d;
    asm("fma.rn.f32x2 %0, %1, %2, %3;" : "=l"(d) : "l"(a), "l"(b), "l"(c));
    return d;
}
__device__ __forceinline__ float lo32(unsigned long long x) { return __uint_as_float((unsigned)x); }
__device__ __forceinline__ float hi32(unsigned long long x) { return __uint_as_float((unsigned)(x >> 32)); }
__device__ __forceinline__ unsigned long long pk2(float a, float b) {
    return (unsigned long long)__float_as_uint(a) | ((unsigned long long)__float_as_uint(b) << 32);
}

#define NEG1X2 0xBF800000BF800000ULL   /* (-1, -1) */
#define BIGX2  0x5F0000005F000000ULL   /* (2^63, 2^63) */

// =====================================================================
// Forward: VALUE = warps 0-1 (64 threads, thread k reduces all 64 preds);
// BP = warps 2-11, float-key first-index argmax with PASS-LOCAL indices:
// per 16-pred pass, key = RN(dp*2^63 + local_j) with constant idxp[8];
// pass min-key + 16*g afterwards (exact for winners: keys <= 15;
// losers stay ~2^53). Cross-pass fmin = absolute first-index argmax.
// Heavy bp rows on SMSP 2,3 (19/4/19/4/18).
// =====================================================================
__global__ void __launch_bounds__(384, 1) fwd_kernel(const float* __restrict__ pot,
                                                     const float* __restrict__ trans) {
    extern __shared__ char smraw[];
    Smem* sm = (Smem*)smraw;

    const int b    = blockIdx.x;
    const int tid  = threadIdx.x;
    const int lane = tid & 31;
    const int wid  = tid >> 5;
    const bool isVal = (tid < 64);

    int k;
    if (isVal) k = tid;
    else       k = lane + (((wid - 2) & 1) ? 32 : 0);

    unsigned long long trp[32];
#pragma unroll
    for (int i = 0; i < 32; ++i)
        trp[i] = pk2(trans[(2 * i) * KK + k], trans[(2 * i + 1) * KK + k]);

    // bp-only: pass-local packed index constants (j, j+1), j = 0..15
    unsigned long long idxp[8];
    if (!isVal) {
#pragma unroll
        for (int i = 0; i < 8; ++i)
            idxp[i] = pk2((float)(2 * i), (float)(2 * i + 1));
    }

    int rstart = 0, rcnt = 0;
    if (!isVal) {
        int pi = (wid - 2) >> 1;
        if      (pi == 0) { rstart = 0;  rcnt = 19; }   // w2,w3   SMSP 2,3
        else if (pi == 1) { rstart = 19; rcnt = 4;  }   // w4,w5   SMSP 0,1
        else if (pi == 2) { rstart = 23; rcnt = 19; }   // w6,w7   SMSP 2,3
        else if (pi == 3) { rstart = 42; rcnt = 4;  }   // w8,w9   SMSP 0,1
        else              { rstart = 46; rcnt = 18; }   // w10,w11 SMSP 2,3
    }

    const float* pbm = pot + (size_t)b * TT * KK;

    if (isVal) {
        uint32_t s0 = (uint32_t)__cvta_generic_to_shared(sm->ebuf[0]);
        uint32_t s1 = (uint32_t)__cvta_generic_to_shared(sm->ebuf[1]);
#pragma unroll
        for (int i = 0; i < 16; ++i)
            cpasync16(s0 + (i * 64 + tid) * 16, pbm + (i * 64 + tid) * 4);
        cpasync_commit();
#pragma unroll
        for (int i = 0; i < 16; ++i)
            cpasync16(s1 + (i * 64 + tid) * 16, pbm + CHUNK * KK + (i * 64 + tid) * 4);
        cpasync_commit();
        cpasync_wait1();
    }
    __syncthreads();
    if (isVal)
        sm->aslab[0][KK + k] = sm->ebuf[0][k];

    for (int p = 0; p <= NCH; ++p) {
        const int pb = p & 1;

        if (isVal && p < NCH) {
            if (p > 0)
                sm->aslab[pb][k] = sm->aslab[pb ^ 1][CHUNK * KK + k];
            asm volatile("bar.sync 1, 64;" ::: "memory");

            const int r0 = (p == 0) ? 1 : 0;
            for (int r = r0; r < CHUNK; ++r) {
                const ulonglong2* arow = (const ulonglong2*)(sm->aslab[pb] + r * KK);
                float emit = sm->ebuf[pb][r * KK + k];

                float gm[4];
#pragma unroll
                for (int g = 0; g < 4; ++g) {
                    ulonglong2 s0 = arow[4 * g + 0], s1 = arow[4 * g + 1];
                    ulonglong2 s2 = arow[4 * g + 2], s3 = arow[4 * g + 3];
                    unsigned long long v0 = addx2(s0.x, trp[8 * g + 0]);
                    unsigned long long v1 = addx2(s0.y, trp[8 * g + 1]);
                    unsigned long long v2 = addx2(s1.x, trp[8 * g + 2]);
                    unsigned long long v3 = addx2(s1.y, trp[8 * g + 3]);
                    unsigned long long v4 = addx2(s2.x, trp[8 * g + 4]);
                    unsigned long long v5 = addx2(s2.y, trp[8 * g + 5]);
                    unsigned long long v6 = addx2(s3.x, trp[8 * g + 6]);
                    unsigned long long v7 = addx2(s3.y, trp[8 * g + 7]);
                    float m0 = fmaxf(lo32(v0), hi32(v0));
                    float m1 = fmaxf(lo32(v1), hi32(v1));
                    float m2 = fmaxf(lo32(v2), hi32(v2));
                    float m3 = fmaxf(lo32(v3), hi32(v3));
                    float m4 = fmaxf(lo32(v4), hi32(v4));
                    float m5 = fmaxf(lo32(v5), hi32(v5));
                    float m6 = fmaxf(lo32(v6), hi32(v6));
                    float m7 = fmaxf(lo32(v7), hi32(v7));
                    m0 = fmaxf(m0, m1); m2 = fmaxf(m2, m3);
                    m4 = fmaxf(m4, m5); m6 = fmaxf(m6, m7);
                    gm[g] = fmaxf(fmaxf(m0, m2), fmaxf(m4, m6));
                }
                float best = fmaxf(fmaxf(gm[0], gm[1]), fmaxf(gm[2], gm[3]));

                sm->bslab[pb][r * KK + k]       = best;
                sm->aslab[pb][(r + 1) * KK + k] = best + emit;
                asm volatile("bar.sync 1, 64;" ::: "memory");
            }

            if (p == NCH - 1 && tid == 0) {
                const float* fin = sm->aslab[pb] + CHUNK * KK;
                float bv = fin[0]; int bk = 0;
#pragma unroll
                for (int kk = 1; kk < KK; ++kk) {
                    float vv = fin[kk];
                    if (vv > bv) { bv = vv; bk = kk; }
                }
                g_lasttag[b] = bk;
            }

            if (p + 1 < NCH) {
                if (p + 2 < NCH) {
                    uint32_t sn = (uint32_t)__cvta_generic_to_shared(sm->ebuf[pb]);
                    const float* gsrc = pbm + (size_t)(p + 2) * CHUNK * KK;
#pragma unroll
                    for (int i = 0; i < 16; ++i)
                        cpasync16(sn + (i * 64 + tid) * 16, gsrc + (i * 64 + tid) * 4);
                }
                cpasync_commit();
                cpasync_wait1();
            }
        }

        if (!isVal && p >= 1) {
            const int q  = p - 1;
            const int qb = q & 1;

            for (int rr = 0; rr < rcnt; ++rr) {
                const int r = rstart + rr;
                if (q == 0 && r == 0) {
                    sm->bps[qb][k] = (uint8_t)k;   // placeholder (never applied)
                    continue;
                }
                const ulonglong2* arow = (const ulonglong2*)(sm->aslab[qb] + r * KK);
                float bestv = sm->bslab[qb][r * KK + k];
                unsigned long long bestp = pk2(bestv, bestv);

                float km[4];
#pragma unroll
                for (int g = 0; g < 4; ++g) {   // 16 preds per pass
                    ulonglong2 s0 = arow[4 * g + 0], s1 = arow[4 * g + 1];
                    ulonglong2 s2 = arow[4 * g + 2], s3 = arow[4 * g + 3];
                    unsigned long long vv[8];
                    vv[0] = addx2(s0.x, trp[8 * g + 0]);
                    vv[1] = addx2(s0.y, trp[8 * g + 1]);
                    vv[2] = addx2(s1.x, trp[8 * g + 2]);
                    vv[3] = addx2(s1.y, trp[8 * g + 3]);
                    vv[4] = addx2(s2.x, trp[8 * g + 4]);
                    vv[5] = addx2(s2.y, trp[8 * g + 5]);
                    vv[6] = addx2(s3.x, trp[8 * g + 6]);
                    vv[7] = addx2(s3.y, trp[8 * g + 7]);
                    float f[8];
#pragma unroll
                    for (int i = 0; i < 8; ++i) {
                        unsigned long long dp = fma2(vv[i], NEG1X2, bestp); // best - v
                        unsigned long long kp = fma2(dp, BIGX2, idxp[i]);   // local j
                        f[i] = fminf(lo32(kp), hi32(kp));
                    }
                    f[0] = fminf(f[0], f[1]); f[2] = fminf(f[2], f[3]);
                    f[4] = fminf(f[4], f[5]); f[6] = fminf(f[6], f[7]);
                    float kml = fminf(fminf(f[0], f[2]), fminf(f[4], f[6]));
                    km[g] = kml + (float)(16 * g);   // absolute index (exact <= 63)
                }
                float kmin = fminf(fminf(km[0], km[1]), fminf(km[2], km[3]));
                sm->bps[qb][r * KK + k] = (uint8_t)(int)kmin;
            }

            asm volatile("bar.sync 2, 320;" ::: "memory");
            {
                const int bpt = tid - 64;
                if (bpt < 256) {
                    uint4* dst = (uint4*)(g_bp + (size_t)b * TT * KK +
                                          (size_t)q * CHUNK * KK);
                    dst[bpt] = ((const uint4*)sm->bps[qb])[bpt];
                }
            }
        }
        __syncthreads();
    }
}

// =====================================================================
// Parallel backward (R15, passing): compose chunk maps -> boundary
// chase -> warp-parallel chunk walks -> lengths.
// =====================================================================
__global__ __launch_bounds__(256) void bwd_kernel(const int* __restrict__ mask,
                                                  float* __restrict__ out) {
    const int b    = blockIdx.x;
    const int tid  = threadIdx.x;
    const int wid  = tid >> 5;
    const int lane = tid & 31;

    __shared__ __align__(16) uint8_t cbuf[8][CHUNK * KK];  // 32 KB chunk buffers
    __shared__ __align__(16) uint8_t maps[NCH * KK];       // 4 KB composed maps
    __shared__ int   btag[NCH];
    __shared__ float tagbuf[8][CHUNK];

    const uint8_t* bpb = g_bp + (size_t)b * TT * KK;

    // ---- Phase A: compose 8 chunks per warp ----
    for (int i = 0; i < 8; ++i) {
        const int c = wid * 8 + i;
        const uint4* src = (const uint4*)(bpb + (size_t)c * CHUNK * KK);
        uint4* dst = (uint4*)cbuf[wid];
#pragma unroll
        for (int j = 0; j < 8; ++j) dst[lane + 32 * j] = src[lane + 32 * j];
        __syncwarp();

        int f0 = 2 * lane, f1 = 2 * lane + 1;   // identity seeds
#pragma unroll 4
        for (int r = CHUNK - 1; r >= 0; --r) {
            const uint8_t* row = cbuf[wid] + r * KK;
            f0 = row[f0];
            f1 = row[f1];
        }
        *(uint16_t*)(maps + c * KK + 2 * lane) = (uint16_t)(f0 | (f1 << 8));
        __syncwarp();
    }
    __syncthreads();

    // ---- Phase B: boundary chase ----
    if (tid == 0) {
        int cur = g_lasttag[b];
        btag[NCH - 1] = cur;
        for (int c = NCH - 1; c >= 1; --c) {
            cur = maps[c * KK + cur];
            btag[c - 1] = cur;
        }
    }
    __syncthreads();

    // ---- Phase C: parallel chunk walks ----
    for (int i = 0; i < 8; ++i) {
        const int c = wid * 8 + i;
        const uint4* src = (const uint4*)(bpb + (size_t)c * CHUNK * KK);
        uint4* dst = (uint4*)cbuf[wid];
#pragma unroll
        for (int j = 0; j < 8; ++j) dst[lane + 32 * j] = src[lane + 32 * j];
        __syncwarp();

        if (lane == 0) {
            int cur = btag[c];
            tagbuf[wid][CHUNK - 1] = (float)cur;
            for (int r = CHUNK - 1; r >= 1; --r) {
                cur = cbuf[wid][r * KK + cur];
                tagbuf[wid][r - 1] = (float)cur;
            }
        }
        __syncwarp();

        float2 o;
        o.x = tagbuf[wid][2 * lane];
        o.y = tagbuf[wid][2 * lane + 1];
        *(float2*)(out + (size_t)b * TT + c * CHUNK + 2 * lane) = o;
        __syncwarp();
    }

    // ---- Phase D: sequence length ----
    {
        int s = 0;
        const int4* m = (const int4*)(mask + (size_t)b * TT);
        for (int i = tid; i < TT / 4; i += 256) {
            int4 v = m[i];
            s += v.x + v.y + v.z + v.w;
        }
#pragma unroll
        for (int off = 16; off; off >>= 1) s += __shfl_xor_sync(0xffffffffu, s, off);
        __shared__ int red[8];
        if ((tid & 31) == 0) red[tid >> 5] = s;
        __syncthreads();
        if (tid == 0) {
            int tot = 0;
#pragma unroll
            for (int i = 0; i < 8; ++i) tot += red[i];
            out[(size_t)BB * TT + b] = (float)tot;
        }
    }
}

// =====================================================================
extern "C" void kernel_launch(void* const* d_in, const int* in_sizes, int n_in,
                              void* d_out, int out_size) {
    const float* pot   = nullptr;
    const float* trans = nullptr;
    const int*   mask  = nullptr;
    for (int i = 0; i < n_in; ++i) {
        if      (in_sizes[i] == BB * TT * KK) pot   = (const float*)d_in[i];
        else if (in_sizes[i] == KK * KK)      trans = (const float*)d_in[i];
        else if (in_sizes[i] == BB * TT)      mask  = (const int*)  d_in[i];
    }
    float* out = (float*)d_out;   // [tags (128*4096) | lengths (128)] as f32

    cudaFuncSetAttribute(fwd_kernel, cudaFuncAttributeMaxDynamicSharedMemorySize,
                         (int)sizeof(Smem));
    fwd_kernel<<<BB, 384, sizeof(Smem)>>>(pot, trans);
    bwd_kernel<<<BB, 256>>>(mask, out);
}